// round 12
// baseline (speedup 1.0000x reference)
#include <cuda_runtime.h>
#include <math.h>
#include <stdint.h>

#define NNODES 50000
#define NEDGES 600000
#define DD 128
#define NGRAPHS 512
#define NCLASSES 10
#define NLAYERS 4

// ---------------- scratch (static device globals) ---------------------------
__device__ float d_h[NNODES * DD];
__device__ float d_m[NNODES * DD];
__device__ float d_agg[NNODES * DD];
__device__ float d_gi[NNODES * 3 * DD];
__device__ float d_gh[NNODES * 3 * DD];
__device__ float d_wB1[NLAYERS * 512 * DD];   // [Whh(384) ; Ws^T(128)] per layer
__device__ int   d_off[NNODES + 1];
__device__ int   d_cnt[NNODES];
__device__ int   d_csc[NEDGES];
__device__ float d_pool[NGRAPHS * DD];
__device__ float d_gcnt[NGRAPHS];
__device__ float d_logits[NGRAPHS * NCLASSES];
__device__ int   d_is64;

// ---------------- tf32 helpers ------------------------------------------------
__device__ __forceinline__ uint32_t f2tf32(float x) {
    uint32_t r;
    asm("cvt.rna.tf32.f32 %0, %1;" : "=r"(r) : "f"(x));
    return r;
}
__device__ __forceinline__ float rna(float x) {
    return __uint_as_float(f2tf32(x));
}
__device__ __forceinline__ void mma_tf32(float* c, const uint32_t* a, const uint32_t* b) {
    asm volatile(
        "mma.sync.aligned.m16n8k8.row.col.f32.tf32.tf32.f32 "
        "{%0,%1,%2,%3},{%4,%5,%6,%7},{%8,%9},{%0,%1,%2,%3};"
        : "+f"(c[0]), "+f"(c[1]), "+f"(c[2]), "+f"(c[3])
        : "r"(a[0]), "r"(a[1]), "r"(a[2]), "r"(a[3]), "r"(b[0]), "r"(b[1]));
}

// ---------------- index dtype detection ---------------------------------------
__global__ void detect_kernel(const void* __restrict__ ei) {
    __shared__ int nz;
    if (threadIdx.x == 0) nz = 0;
    __syncthreads();
    const int* w = (const int*)ei;
    int v = w[2 * threadIdx.x + 1];
    if (v != 0) atomicAdd(&nz, 1);
    __syncthreads();
    if (threadIdx.x == 0) d_is64 = (nz == 0) ? 1 : 0;
}
__device__ __forceinline__ int load_idx(const void* p, int i) {
    return d_is64 ? (int)((const long long*)p)[i] : ((const int*)p)[i];
}

// ---------------- utility kernels ---------------------------------------------
__global__ void copy_h_kernel(const float* __restrict__ src, int n) {
    int i = blockIdx.x * blockDim.x + threadIdx.x;
    if (i < n) d_h[i] = src[i];
}
__global__ void zero_cnt_kernel(int n) {
    int i = blockIdx.x * blockDim.x + threadIdx.x;
    if (i < n) d_cnt[i] = 0;
}
__global__ void zero_pool_kernel() {
    int i = blockIdx.x * blockDim.x + threadIdx.x;
    if (i < NGRAPHS * DD) d_pool[i] = 0.f;
    if (i < NGRAPHS) d_gcnt[i] = 0.f;
}
// B1 = [Whh (rows 0..383) ; Ws^T (rows 384..511)] per layer, fp32
__global__ void conv_wB1_kernel(const float* __restrict__ Whh, const float* __restrict__ Ws) {
    int i = blockIdx.x * blockDim.x + threadIdx.x;
    if (i >= NLAYERS * 512 * DD) return;
    int l = i / (512 * DD);
    int r = (i / DD) % 512;
    int k = i % DD;
    d_wB1[i] = (r < 384) ? Whh[(size_t)l * 384 * DD + r * DD + k]
                         : Ws[(size_t)l * DD * DD + k * DD + (r - 384)];
}

// ---------------- CSC build ----------------------------------------------------
__global__ void count_kernel(const void* __restrict__ ei, int n_edges) {
    int e = blockIdx.x * blockDim.x + threadIdx.x;
    if (e >= n_edges) return;
    int dst = load_idx(ei, n_edges + e);
    if (dst >= 0 && dst < NNODES) atomicAdd(&d_cnt[dst], 1);
}
__global__ void scan_kernel(int n) {
    __shared__ int tmp[1024];
    __shared__ int carry;
    int tid = threadIdx.x;
    if (tid == 0) carry = 0;
    __syncthreads();
    for (int base = 0; base < n; base += 1024) {
        int v = (base + tid < n) ? d_cnt[base + tid] : 0;
        tmp[tid] = v;
        __syncthreads();
        for (int off = 1; off < 1024; off <<= 1) {
            int t = (tid >= off) ? tmp[tid - off] : 0;
            __syncthreads();
            tmp[tid] += t;
            __syncthreads();
        }
        int excl = tmp[tid] - v;
        if (base + tid < n) d_off[base + tid] = carry + excl;
        __syncthreads();
        if (tid == 1023) carry += tmp[1023];
        __syncthreads();
    }
    if (tid == 0) d_off[n] = carry;
}
__global__ void fill_kernel(const void* __restrict__ ei, int n_edges) {
    int e = blockIdx.x * blockDim.x + threadIdx.x;
    if (e >= n_edges) return;
    int dst = load_idx(ei, n_edges + e);
    int src = load_idx(ei, e);
    if (dst < 0 || dst >= NNODES || src < 0 || src >= NNODES) return;
    int pos = d_off[dst] + atomicAdd(&d_cnt[dst], 1);
    if (pos < NEDGES) d_csc[pos] = src;
}

// ---------------- aggregation: one warp per node, float4 per lane --------------
__global__ void agg_kernel(int n_nodes) {
    int warp = (blockIdx.x * blockDim.x + threadIdx.x) >> 5;
    int lane = threadIdx.x & 31;
    if (warp >= n_nodes) return;
    int s = d_off[warp], e = d_off[warp + 1];
    float4 acc = make_float4(0.f, 0.f, 0.f, 0.f);
    for (int i = s; i < e; i++) {
        int src = d_csc[i];
        float4 v = *(const float4*)(d_m + (size_t)src * DD + lane * 4);
        acc.x += v.x; acc.y += v.y; acc.z += v.z; acc.w += v.w;
    }
    *(float4*)(d_agg + (size_t)warp * DD + lane * 4) = acc;
}

// ---------------- 1xTF32 GEMM: both operands rounded once ----------------------
// Double-buffered BK=16 pipeline with register prefetch; one sync per chunk.
// C[M,:] = A[M,128] @ B[N,128]^T (+bias); cols < N1 -> C1, else C2 (stride 128).
#define SW 20   // padded row width; (20g+tg) mod 32 conflict-free
__device__ __forceinline__ void gemm_tf32_body(
    const float* __restrict__ A, const float* __restrict__ B,
    const float* __restrict__ bias, float* __restrict__ C1, int N1,
    float* __restrict__ C2, int M)
{
    __shared__ float sA[2][128][SW];
    __shared__ float sB[2][64][SW];
    int tid = threadIdx.x, lane = tid & 31, wid = tid >> 5;
    int g = lane >> 2, tg = lane & 3;
    int m0 = blockIdx.x * 128, n0 = blockIdx.y * 64;
    int wm0 = (wid & 3) * 32, wn0 = (wid >> 2) * 32;

    int br = tid >> 2, bq = tid & 3;   // B staging row/quad

    float c[2][4][4] = {};
    float4 pa[2], pb;

    // prefetch chunk 0
#pragma unroll
    for (int t = 0; t < 2; t++) {
        int row = ((tid + t * 256) >> 2);
        int q = (tid + t * 256) & 3;
        int gr = m0 + row;
        pa[t] = (gr < M) ? *(const float4*)&A[(size_t)gr * 128 + q * 4]
                         : make_float4(0.f, 0.f, 0.f, 0.f);
    }
    pb = *(const float4*)&B[(size_t)(n0 + br) * 128 + bq * 4];

    int p = 0;
    for (int kc = 0; kc < 8; kc++) {
        // store staged chunk (single tf32 round for both operands)
#pragma unroll
        for (int t = 0; t < 2; t++) {
            int row = ((tid + t * 256) >> 2);
            int q = (tid + t * 256) & 3;
            sA[p][row][q * 4 + 0] = rna(pa[t].x);
            sA[p][row][q * 4 + 1] = rna(pa[t].y);
            sA[p][row][q * 4 + 2] = rna(pa[t].z);
            sA[p][row][q * 4 + 3] = rna(pa[t].w);
        }
        sB[p][br][bq * 4 + 0] = rna(pb.x);
        sB[p][br][bq * 4 + 1] = rna(pb.y);
        sB[p][br][bq * 4 + 2] = rna(pb.z);
        sB[p][br][bq * 4 + 3] = rna(pb.w);
        __syncthreads();

        // prefetch next chunk (LDG in flight during MMAs)
        if (kc < 7) {
            int k0 = (kc + 1) * 16;
#pragma unroll
            for (int t = 0; t < 2; t++) {
                int row = ((tid + t * 256) >> 2);
                int q = (tid + t * 256) & 3;
                int gr = m0 + row;
                pa[t] = (gr < M) ? *(const float4*)&A[(size_t)gr * 128 + k0 + q * 4]
                                 : make_float4(0.f, 0.f, 0.f, 0.f);
            }
            pb = *(const float4*)&B[(size_t)(n0 + br) * 128 + k0 + bq * 4];
        }

#pragma unroll
        for (int ks = 0; ks < 16; ks += 8) {
            // m16n8k8 tf32 fragments:
            //  a0=A[g][tg] a1=A[g+8][tg] a2=A[g][tg+4] a3=A[g+8][tg+4]
            //  b0=B[tg][g] b1=B[tg+4][g]  (B stored [n][k])
            uint32_t ah[2][4], bh[4][2];
#pragma unroll
            for (int mt = 0; mt < 2; mt++) {
                int r0 = wm0 + mt * 16 + g;
                ah[mt][0] = __float_as_uint(sA[p][r0][ks + tg]);
                ah[mt][1] = __float_as_uint(sA[p][r0 + 8][ks + tg]);
                ah[mt][2] = __float_as_uint(sA[p][r0][ks + tg + 4]);
                ah[mt][3] = __float_as_uint(sA[p][r0 + 8][ks + tg + 4]);
            }
#pragma unroll
            for (int nt = 0; nt < 4; nt++) {
                int r = wn0 + nt * 8 + g;
                bh[nt][0] = __float_as_uint(sB[p][r][ks + tg]);
                bh[nt][1] = __float_as_uint(sB[p][r][ks + tg + 4]);
            }
#pragma unroll
            for (int mt = 0; mt < 2; mt++)
#pragma unroll
                for (int nt = 0; nt < 4; nt++)
                    mma_tf32(c[mt][nt], ah[mt], bh[nt]);
        }
        p ^= 1;
    }

#pragma unroll
    for (int mt = 0; mt < 2; mt++)
#pragma unroll
        for (int nt = 0; nt < 4; nt++)
#pragma unroll
            for (int hr = 0; hr < 2; hr++) {
                int row = m0 + wm0 + mt * 16 + g + hr * 8;
                if (row >= M) continue;
                int col = n0 + wn0 + nt * 8 + tg * 2;
                float v0 = c[mt][nt][hr * 2 + 0];
                float v1 = c[mt][nt][hr * 2 + 1];
                if (col < N1) {
                    if (bias) { v0 += bias[col]; v1 += bias[col + 1]; }
                    *(float2*)&C1[(size_t)row * N1 + col] = make_float2(v0, v1);
                } else {
                    *(float2*)&C2[(size_t)row * DD + (col - N1)] = make_float2(v0, v1);
                }
            }
}

// fused: [gh | m] = h @ [Whh^T | Ws]
__global__ __launch_bounds__(256) void gemm1_kernel(const float* __restrict__ bhh, int l, int M) {
    gemm_tf32_body(d_h, d_wB1 + (size_t)l * 512 * DD, bhh, d_gh, 384, d_m, M);
}
// gi = agg @ Wih^T + bih   (Wih already [384,128] row-major = B[n][k])
__global__ __launch_bounds__(256) void gemm2_kernel(const float* __restrict__ Wih,
                                                    const float* __restrict__ bih, int M) {
    gemm_tf32_body(d_agg, Wih, bih, d_gi, 384, nullptr, M);
}

// ---------------- fused GRU gates + ReLU (float4 vectorized) -------------------
__global__ void gru_kernel(int n_nodes) {
    int idx = blockIdx.x * blockDim.x + threadIdx.x;   // one per 4 elements
    int total = n_nodes * (DD / 4);
    if (idx >= total) return;
    int i = idx / (DD / 4), jq = idx % (DD / 4);
    const float* gir = d_gi + (size_t)i * 3 * DD + jq * 4;
    const float* ghr = d_gh + (size_t)i * 3 * DD + jq * 4;
    float4 ir = *(const float4*)(gir);
    float4 iz = *(const float4*)(gir + DD);
    float4 in_ = *(const float4*)(gir + 2 * DD);
    float4 hr = *(const float4*)(ghr);
    float4 hz = *(const float4*)(ghr + DD);
    float4 hn = *(const float4*)(ghr + 2 * DD);
    float4 hv = *(const float4*)(d_h + (size_t)i * DD + jq * 4);
    float4 o;
#define GRU1(f)                                                        \
    {                                                                  \
        float r = 1.f / (1.f + expf(-(ir.f + hr.f)));                  \
        float z = 1.f / (1.f + expf(-(iz.f + hz.f)));                  \
        float nn = tanhf(in_.f + r * hn.f);                            \
        o.f = fmaxf((1.f - z) * nn + z * hv.f, 0.f);                   \
    }
    GRU1(x) GRU1(y) GRU1(z) GRU1(w)
#undef GRU1
    *(float4*)(d_h + (size_t)i * DD + jq * 4) = o;
}

// ---------------- mean pool -----------------------------------------------------
__global__ void pool_kernel(const void* __restrict__ batch, int n_nodes) {
    int idx = blockIdx.x * blockDim.x + threadIdx.x;
    if (idx >= n_nodes * DD) return;
    int i = idx / DD, j = idx % DD;
    int g = load_idx(batch, i);
    if (g < 0 || g >= NGRAPHS) return;
    atomicAdd(&d_pool[g * DD + j], d_h[idx]);
    if (j == 0) atomicAdd(&d_gcnt[g], 1.f);
}

// ---------------- readout FC1(elu) + FC2 ----------------------------------------
__global__ void readout_kernel(const float* __restrict__ fc1w, const float* __restrict__ fc1b,
                               const float* __restrict__ fc2w, const float* __restrict__ fc2b) {
    int g = blockIdx.x;
    int j = threadIdx.x;
    __shared__ float hg[DD];
    __shared__ float h2[DD];
    float c = fmaxf(d_gcnt[g], 1.f);
    hg[j] = d_pool[g * DD + j] / c;
    __syncthreads();
    float a = fc1b[j];
#pragma unroll 4
    for (int k = 0; k < DD; k++) a += hg[k] * fc1w[j * DD + k];
    h2[j] = (a > 0.f) ? a : expm1f(a);
    __syncthreads();
    if (j < NCLASSES) {
        float s = fc2b[j];
#pragma unroll 4
        for (int k = 0; k < DD; k++) s += h2[k] * fc2w[j * DD + k];
        d_logits[g * NCLASSES + j] = s;
    }
}

// ---------------- log_softmax over axis 0 ---------------------------------------
__global__ void lsm_kernel(float* __restrict__ out) {
    int c = blockIdx.x;
    int g = threadIdx.x;
    __shared__ float sh[NGRAPHS];
    float x = d_logits[g * NCLASSES + c];
    sh[g] = x;
    __syncthreads();
    for (int off = NGRAPHS / 2; off > 0; off >>= 1) {
        if (g < off) sh[g] = fmaxf(sh[g], sh[g + off]);
        __syncthreads();
    }
    float mx = sh[0];
    __syncthreads();
    sh[g] = expf(x - mx);
    __syncthreads();
    for (int off = NGRAPHS / 2; off > 0; off >>= 1) {
        if (g < off) sh[g] += sh[g + off];
        __syncthreads();
    }
    float lse = mx + logf(sh[0]);
    out[g * NCLASSES + c] = x - lse;
}

// ---------------- launch ---------------------------------------------------------
extern "C" void kernel_launch(void* const* d_in, const int* in_sizes, int n_in,
                              void* d_out, int out_size) {
    const float* h_in  = (const float*)d_in[0];
    const void*  ei    = d_in[1];
    const void*  batch = d_in[3];
    const float* Ws   = (const float*)d_in[4];
    const float* Wih  = (const float*)d_in[5];
    const float* Whh  = (const float*)d_in[6];
    const float* bih  = (const float*)d_in[7];
    const float* bhh  = (const float*)d_in[8];
    const float* fc1w = (const float*)d_in[9];
    const float* fc1b = (const float*)d_in[10];
    const float* fc2w = (const float*)d_in[11];
    const float* fc2b = (const float*)d_in[12];
    float* out = (float*)d_out;

    int n_nodes = in_sizes[0] / DD;
    int n_edges = in_sizes[1] / 2;
    int nh = n_nodes * DD;

    detect_kernel<<<1, 128>>>(ei);
    copy_h_kernel<<<(nh + 255) / 256, 256>>>(h_in, nh);
    conv_wB1_kernel<<<(NLAYERS * 512 * DD + 255) / 256, 256>>>(Whh, Ws);

    // CSC build (once; reused across layers)
    zero_cnt_kernel<<<(n_nodes + 255) / 256, 256>>>(n_nodes);
    count_kernel<<<(n_edges + 255) / 256, 256>>>(ei, n_edges);
    scan_kernel<<<1, 1024>>>(n_nodes);
    zero_cnt_kernel<<<(n_nodes + 255) / 256, 256>>>(n_nodes);
    fill_kernel<<<(n_edges + 255) / 256, 256>>>(ei, n_edges);

    dim3 grid1((n_nodes + 127) / 128, 8);   // 512 output cols: [gh(384) | m(128)]
    dim3 grid2((n_nodes + 127) / 128, 6);   // 384 output cols: gi

    for (int l = 0; l < NLAYERS; l++) {
        gemm1_kernel<<<grid1, 256>>>(bhh + (size_t)l * 3 * DD, l, n_nodes);
        agg_kernel<<<(n_nodes * 32 + 255) / 256, 256>>>(n_nodes);
        gemm2_kernel<<<grid2, 256>>>(Wih + (size_t)l * 384 * DD, bih + (size_t)l * 3 * DD, n_nodes);
        gru_kernel<<<(nh / 4 + 255) / 256, 256>>>(n_nodes);
    }

    zero_pool_kernel<<<(NGRAPHS * DD + 255) / 256, 256>>>();
    pool_kernel<<<(nh + 255) / 256, 256>>>(batch, n_nodes);
    readout_kernel<<<NGRAPHS, DD>>>(fc1w, fc1b, fc2w, fc2b);
    lsm_kernel<<<NCLASSES, NGRAPHS>>>(out);
}

// round 13
// speedup vs baseline: 1.5642x; 1.5642x over previous
#include <cuda_runtime.h>
#include <math.h>
#include <stdint.h>

#define NNODES 50000
#define NEDGES 600000
#define DD 128
#define NGRAPHS 512
#define NCLASSES 10
#define NLAYERS 4

// ---------------- scratch (static device globals) ---------------------------
__device__ float d_h[NNODES * DD];
__device__ float d_m[NNODES * DD];
__device__ float d_agg[NNODES * DD];
__device__ float d_gi[NNODES * 3 * DD];
__device__ float d_gh[NNODES * 3 * DD];
__device__ float d_wB1[NLAYERS * 512 * DD];   // [Whh(384) ; Ws^T(128)] per layer
__device__ int   d_off[NNODES + 1];
__device__ int   d_cnt[NNODES];
__device__ int   d_csc[NEDGES];
__device__ float d_pool[NGRAPHS * DD];
__device__ float d_gcnt[NGRAPHS];
__device__ float d_logits[NGRAPHS * NCLASSES];
__device__ int   d_is64;

// ---------------- tf32 helpers ------------------------------------------------
__device__ __forceinline__ uint32_t f2tf32(float x) {
    uint32_t r;
    asm("cvt.rna.tf32.f32 %0, %1;" : "=r"(r) : "f"(x));
    return r;
}
__device__ __forceinline__ float rna(float x) {
    return __uint_as_float(f2tf32(x));
}
__device__ __forceinline__ void mma_tf32(float* c, const uint32_t* a, const uint32_t* b) {
    asm volatile(
        "mma.sync.aligned.m16n8k8.row.col.f32.tf32.tf32.f32 "
        "{%0,%1,%2,%3},{%4,%5,%6,%7},{%8,%9},{%0,%1,%2,%3};"
        : "+f"(c[0]), "+f"(c[1]), "+f"(c[2]), "+f"(c[3])
        : "r"(a[0]), "r"(a[1]), "r"(a[2]), "r"(a[3]), "r"(b[0]), "r"(b[1]));
}

// ---------------- index dtype detection ---------------------------------------
__global__ void detect_kernel(const void* __restrict__ ei) {
    __shared__ int nz;
    if (threadIdx.x == 0) nz = 0;
    __syncthreads();
    const int* w = (const int*)ei;
    int v = w[2 * threadIdx.x + 1];
    if (v != 0) atomicAdd(&nz, 1);
    __syncthreads();
    if (threadIdx.x == 0) d_is64 = (nz == 0) ? 1 : 0;
}
__device__ __forceinline__ int load_idx(const void* p, int i) {
    return d_is64 ? (int)((const long long*)p)[i] : ((const int*)p)[i];
}

// ---------------- utility kernels ---------------------------------------------
__global__ void copy_h_kernel(const float* __restrict__ src, int n) {
    int i = blockIdx.x * blockDim.x + threadIdx.x;
    if (i < n) d_h[i] = src[i];
}
__global__ void zero_cnt_kernel(int n) {
    int i = blockIdx.x * blockDim.x + threadIdx.x;
    if (i < n) d_cnt[i] = 0;
}
__global__ void zero_pool_kernel() {
    int i = blockIdx.x * blockDim.x + threadIdx.x;
    if (i < NGRAPHS * DD) d_pool[i] = 0.f;
    if (i < NGRAPHS) d_gcnt[i] = 0.f;
}
// B1 = [Whh (rows 0..383) ; Ws^T (rows 384..511)] per layer, fp32
__global__ void conv_wB1_kernel(const float* __restrict__ Whh, const float* __restrict__ Ws) {
    int i = blockIdx.x * blockDim.x + threadIdx.x;
    if (i >= NLAYERS * 512 * DD) return;
    int l = i / (512 * DD);
    int r = (i / DD) % 512;
    int k = i % DD;
    d_wB1[i] = (r < 384) ? Whh[(size_t)l * 384 * DD + r * DD + k]
                         : Ws[(size_t)l * DD * DD + k * DD + (r - 384)];
}

// ---------------- CSC build ----------------------------------------------------
__global__ void count_kernel(const void* __restrict__ ei, int n_edges) {
    int e = blockIdx.x * blockDim.x + threadIdx.x;
    if (e >= n_edges) return;
    int dst = load_idx(ei, n_edges + e);
    if (dst >= 0 && dst < NNODES) atomicAdd(&d_cnt[dst], 1);
}
__global__ void scan_kernel(int n) {
    __shared__ int tmp[1024];
    __shared__ int carry;
    int tid = threadIdx.x;
    if (tid == 0) carry = 0;
    __syncthreads();
    for (int base = 0; base < n; base += 1024) {
        int v = (base + tid < n) ? d_cnt[base + tid] : 0;
        tmp[tid] = v;
        __syncthreads();
        for (int off = 1; off < 1024; off <<= 1) {
            int t = (tid >= off) ? tmp[tid - off] : 0;
            __syncthreads();
            tmp[tid] += t;
            __syncthreads();
        }
        int excl = tmp[tid] - v;
        if (base + tid < n) d_off[base + tid] = carry + excl;
        __syncthreads();
        if (tid == 1023) carry += tmp[1023];
        __syncthreads();
    }
    if (tid == 0) d_off[n] = carry;
}
__global__ void fill_kernel(const void* __restrict__ ei, int n_edges) {
    int e = blockIdx.x * blockDim.x + threadIdx.x;
    if (e >= n_edges) return;
    int dst = load_idx(ei, n_edges + e);
    int src = load_idx(ei, e);
    if (dst < 0 || dst >= NNODES || src < 0 || src >= NNODES) return;
    int pos = d_off[dst] + atomicAdd(&d_cnt[dst], 1);
    if (pos < NEDGES) d_csc[pos] = src;
}

// ---------------- aggregation: one warp per node, float4 per lane --------------
__global__ void agg_kernel(int n_nodes) {
    int warp = (blockIdx.x * blockDim.x + threadIdx.x) >> 5;
    int lane = threadIdx.x & 31;
    if (warp >= n_nodes) return;
    int s = d_off[warp], e = d_off[warp + 1];
    float4 acc = make_float4(0.f, 0.f, 0.f, 0.f);
    for (int i = s; i < e; i++) {
        int src = d_csc[i];
        float4 v = *(const float4*)(d_m + (size_t)src * DD + lane * 4);
        acc.x += v.x; acc.y += v.y; acc.z += v.z; acc.w += v.w;
    }
    *(float4*)(d_agg + (size_t)warp * DD + lane * 4) = acc;
}

// ---------------- 1xTF32 GEMM, BK=32 double-buffered ---------------------------
// 16 MMAs between barriers (restores R11's per-sync compute density).
// C[M,:] = A[M,128] @ B[N,128]^T (+bias); cols < N1 -> C1, else C2 (stride 128).
#define SW 36   // padded row width for 32-col chunk; (4g+tg) mod 32 conflict-free
__device__ __forceinline__ void gemm_tf32_body(
    const float* __restrict__ A, const float* __restrict__ B,
    const float* __restrict__ bias, float* __restrict__ C1, int N1,
    float* __restrict__ C2, int M)
{
    __shared__ float sA[2][128][SW];
    __shared__ float sB[2][64][SW];
    int tid = threadIdx.x, lane = tid & 31, wid = tid >> 5;
    int g = lane >> 2, tg = lane & 3;
    int m0 = blockIdx.x * 128, n0 = blockIdx.y * 64;
    int wm0 = (wid & 3) * 32, wn0 = (wid >> 2) * 32;

    float c[2][4][4] = {};
    float4 pa[4], pb[2];

    // prefetch chunk 0 (A: 128x32 = 1024 float4, 4/thread; B: 64x32 = 512, 2/thread)
#pragma unroll
    for (int t = 0; t < 4; t++) {
        int ch = tid + t * 256;
        int row = ch >> 3, q = ch & 7;
        int gr = m0 + row;
        pa[t] = (gr < M) ? *(const float4*)&A[(size_t)gr * 128 + q * 4]
                         : make_float4(0.f, 0.f, 0.f, 0.f);
    }
#pragma unroll
    for (int t = 0; t < 2; t++) {
        int ch = tid + t * 256;
        int row = ch >> 3, q = ch & 7;
        pb[t] = *(const float4*)&B[(size_t)(n0 + row) * 128 + q * 4];
    }

    int p = 0;
    for (int kc = 0; kc < 4; kc++) {
        // store staged chunk with single tf32 round
#pragma unroll
        for (int t = 0; t < 4; t++) {
            int ch = tid + t * 256;
            int row = ch >> 3, q = ch & 7;
            sA[p][row][q * 4 + 0] = rna(pa[t].x);
            sA[p][row][q * 4 + 1] = rna(pa[t].y);
            sA[p][row][q * 4 + 2] = rna(pa[t].z);
            sA[p][row][q * 4 + 3] = rna(pa[t].w);
        }
#pragma unroll
        for (int t = 0; t < 2; t++) {
            int ch = tid + t * 256;
            int row = ch >> 3, q = ch & 7;
            sB[p][row][q * 4 + 0] = rna(pb[t].x);
            sB[p][row][q * 4 + 1] = rna(pb[t].y);
            sB[p][row][q * 4 + 2] = rna(pb[t].z);
            sB[p][row][q * 4 + 3] = rna(pb[t].w);
        }
        __syncthreads();

        // prefetch next chunk (LDG in flight during 16 MMAs)
        if (kc < 3) {
            int k0 = (kc + 1) * 32;
#pragma unroll
            for (int t = 0; t < 4; t++) {
                int ch = tid + t * 256;
                int row = ch >> 3, q = ch & 7;
                int gr = m0 + row;
                pa[t] = (gr < M) ? *(const float4*)&A[(size_t)gr * 128 + k0 + q * 4]
                                 : make_float4(0.f, 0.f, 0.f, 0.f);
            }
#pragma unroll
            for (int t = 0; t < 2; t++) {
                int ch = tid + t * 256;
                int row = ch >> 3, q = ch & 7;
                pb[t] = *(const float4*)&B[(size_t)(n0 + row) * 128 + k0 + q * 4];
            }
        }

#pragma unroll
        for (int ks = 0; ks < 32; ks += 8) {
            // m16n8k8 tf32 fragments:
            //  a0=A[g][tg] a1=A[g+8][tg] a2=A[g][tg+4] a3=A[g+8][tg+4]
            //  b0=B[tg][g] b1=B[tg+4][g]  (B stored [n][k])
            uint32_t ah[2][4], bh[4][2];
#pragma unroll
            for (int mt = 0; mt < 2; mt++) {
                int r0 = wm0 + mt * 16 + g;
                ah[mt][0] = __float_as_uint(sA[p][r0][ks + tg]);
                ah[mt][1] = __float_as_uint(sA[p][r0 + 8][ks + tg]);
                ah[mt][2] = __float_as_uint(sA[p][r0][ks + tg + 4]);
                ah[mt][3] = __float_as_uint(sA[p][r0 + 8][ks + tg + 4]);
            }
#pragma unroll
            for (int nt = 0; nt < 4; nt++) {
                int r = wn0 + nt * 8 + g;
                bh[nt][0] = __float_as_uint(sB[p][r][ks + tg]);
                bh[nt][1] = __float_as_uint(sB[p][r][ks + tg + 4]);
            }
#pragma unroll
            for (int mt = 0; mt < 2; mt++)
#pragma unroll
                for (int nt = 0; nt < 4; nt++)
                    mma_tf32(c[mt][nt], ah[mt], bh[nt]);
        }
        p ^= 1;
    }

#pragma unroll
    for (int mt = 0; mt < 2; mt++)
#pragma unroll
        for (int nt = 0; nt < 4; nt++)
#pragma unroll
            for (int hr = 0; hr < 2; hr++) {
                int row = m0 + wm0 + mt * 16 + g + hr * 8;
                if (row >= M) continue;
                int col = n0 + wn0 + nt * 8 + tg * 2;
                float v0 = c[mt][nt][hr * 2 + 0];
                float v1 = c[mt][nt][hr * 2 + 1];
                if (col < N1) {
                    if (bias) { v0 += bias[col]; v1 += bias[col + 1]; }
                    *(float2*)&C1[(size_t)row * N1 + col] = make_float2(v0, v1);
                } else {
                    *(float2*)&C2[(size_t)row * DD + (col - N1)] = make_float2(v0, v1);
                }
            }
}

// fused: [gh | m] = h @ [Whh^T | Ws]
__global__ __launch_bounds__(256) void gemm1_kernel(const float* __restrict__ bhh, int l, int M) {
    gemm_tf32_body(d_h, d_wB1 + (size_t)l * 512 * DD, bhh, d_gh, 384, d_m, M);
}
// gi = agg @ Wih^T + bih   (Wih already [384,128] row-major = B[n][k])
__global__ __launch_bounds__(256) void gemm2_kernel(const float* __restrict__ Wih,
                                                    const float* __restrict__ bih, int M) {
    gemm_tf32_body(d_agg, Wih, bih, d_gi, 384, nullptr, M);
}

// ---------------- fused GRU gates + ReLU (float4 vectorized) -------------------
__global__ void gru_kernel(int n_nodes) {
    int idx = blockIdx.x * blockDim.x + threadIdx.x;   // one per 4 elements
    int total = n_nodes * (DD / 4);
    if (idx >= total) return;
    int i = idx / (DD / 4), jq = idx % (DD / 4);
    const float* gir = d_gi + (size_t)i * 3 * DD + jq * 4;
    const float* ghr = d_gh + (size_t)i * 3 * DD + jq * 4;
    float4 ir = *(const float4*)(gir);
    float4 iz = *(const float4*)(gir + DD);
    float4 in_ = *(const float4*)(gir + 2 * DD);
    float4 hr = *(const float4*)(ghr);
    float4 hz = *(const float4*)(ghr + DD);
    float4 hn = *(const float4*)(ghr + 2 * DD);
    float4 hv = *(const float4*)(d_h + (size_t)i * DD + jq * 4);
    float4 o;
#define GRU1(f)                                                        \
    {                                                                  \
        float r = 1.f / (1.f + expf(-(ir.f + hr.f)));                  \
        float z = 1.f / (1.f + expf(-(iz.f + hz.f)));                  \
        float nn = tanhf(in_.f + r * hn.f);                            \
        o.f = fmaxf((1.f - z) * nn + z * hv.f, 0.f);                   \
    }
    GRU1(x) GRU1(y) GRU1(z) GRU1(w)
#undef GRU1
    *(float4*)(d_h + (size_t)i * DD + jq * 4) = o;
}

// ---------------- mean pool -----------------------------------------------------
__global__ void pool_kernel(const void* __restrict__ batch, int n_nodes) {
    int idx = blockIdx.x * blockDim.x + threadIdx.x;
    if (idx >= n_nodes * DD) return;
    int i = idx / DD, j = idx % DD;
    int g = load_idx(batch, i);
    if (g < 0 || g >= NGRAPHS) return;
    atomicAdd(&d_pool[g * DD + j], d_h[idx]);
    if (j == 0) atomicAdd(&d_gcnt[g], 1.f);
}

// ---------------- readout FC1(elu) + FC2 ----------------------------------------
__global__ void readout_kernel(const float* __restrict__ fc1w, const float* __restrict__ fc1b,
                               const float* __restrict__ fc2w, const float* __restrict__ fc2b) {
    int g = blockIdx.x;
    int j = threadIdx.x;
    __shared__ float hg[DD];
    __shared__ float h2[DD];
    float c = fmaxf(d_gcnt[g], 1.f);
    hg[j] = d_pool[g * DD + j] / c;
    __syncthreads();
    float a = fc1b[j];
#pragma unroll 4
    for (int k = 0; k < DD; k++) a += hg[k] * fc1w[j * DD + k];
    h2[j] = (a > 0.f) ? a : expm1f(a);
    __syncthreads();
    if (j < NCLASSES) {
        float s = fc2b[j];
#pragma unroll 4
        for (int k = 0; k < DD; k++) s += h2[k] * fc2w[j * DD + k];
        d_logits[g * NCLASSES + j] = s;
    }
}

// ---------------- log_softmax over axis 0 ---------------------------------------
__global__ void lsm_kernel(float* __restrict__ out) {
    int c = blockIdx.x;
    int g = threadIdx.x;
    __shared__ float sh[NGRAPHS];
    float x = d_logits[g * NCLASSES + c];
    sh[g] = x;
    __syncthreads();
    for (int off = NGRAPHS / 2; off > 0; off >>= 1) {
        if (g < off) sh[g] = fmaxf(sh[g], sh[g + off]);
        __syncthreads();
    }
    float mx = sh[0];
    __syncthreads();
    sh[g] = expf(x - mx);
    __syncthreads();
    for (int off = NGRAPHS / 2; off > 0; off >>= 1) {
        if (g < off) sh[g] += sh[g + off];
        __syncthreads();
    }
    float lse = mx + logf(sh[0]);
    out[g * NCLASSES + c] = x - lse;
}

// ---------------- launch ---------------------------------------------------------
extern "C" void kernel_launch(void* const* d_in, const int* in_sizes, int n_in,
                              void* d_out, int out_size) {
    const float* h_in  = (const float*)d_in[0];
    const void*  ei    = d_in[1];
    const void*  batch = d_in[3];
    const float* Ws   = (const float*)d_in[4];
    const float* Wih  = (const float*)d_in[5];
    const float* Whh  = (const float*)d_in[6];
    const float* bih  = (const float*)d_in[7];
    const float* bhh  = (const float*)d_in[8];
    const float* fc1w = (const float*)d_in[9];
    const float* fc1b = (const float*)d_in[10];
    const float* fc2w = (const float*)d_in[11];
    const float* fc2b = (const float*)d_in[12];
    float* out = (float*)d_out;

    int n_nodes = in_sizes[0] / DD;
    int n_edges = in_sizes[1] / 2;
    int nh = n_nodes * DD;

    detect_kernel<<<1, 128>>>(ei);
    copy_h_kernel<<<(nh + 255) / 256, 256>>>(h_in, nh);
    conv_wB1_kernel<<<(NLAYERS * 512 * DD + 255) / 256, 256>>>(Whh, Ws);

    // CSC build (once; reused across layers)
    zero_cnt_kernel<<<(n_nodes + 255) / 256, 256>>>(n_nodes);
    count_kernel<<<(n_edges + 255) / 256, 256>>>(ei, n_edges);
    scan_kernel<<<1, 1024>>>(n_nodes);
    zero_cnt_kernel<<<(n_nodes + 255) / 256, 256>>>(n_nodes);
    fill_kernel<<<(n_edges + 255) / 256, 256>>>(ei, n_edges);

    dim3 grid1((n_nodes + 127) / 128, 8);   // 512 output cols: [gh(384) | m(128)]
    dim3 grid2((n_nodes + 127) / 128, 6);   // 384 output cols: gi

    for (int l = 0; l < NLAYERS; l++) {
        gemm1_kernel<<<grid1, 256>>>(bhh + (size_t)l * 3 * DD, l, n_nodes);
        agg_kernel<<<(n_nodes * 32 + 255) / 256, 256>>>(n_nodes);
        gemm2_kernel<<<grid2, 256>>>(Wih + (size_t)l * 384 * DD, bih + (size_t)l * 3 * DD, n_nodes);
        gru_kernel<<<(nh / 4 + 255) / 256, 256>>>(n_nodes);
    }

    zero_pool_kernel<<<(NGRAPHS * DD + 255) / 256, 256>>>();
    pool_kernel<<<(nh + 255) / 256, 256>>>(batch, n_nodes);
    readout_kernel<<<NGRAPHS, DD>>>(fc1w, fc1b, fc2w, fc2b);
    lsm_kernel<<<NCLASSES, NGRAPHS>>>(out);
}

// round 14
// speedup vs baseline: 1.7206x; 1.1000x over previous
#include <cuda_runtime.h>
#include <math.h>
#include <stdint.h>

#define NNODES 50000
#define NEDGES 600000
#define DD 128
#define NGRAPHS 512
#define NCLASSES 10
#define NLAYERS 4

// ---------------- scratch (static device globals) ---------------------------
__device__ float d_h[NNODES * DD];
__device__ float d_m[NNODES * DD];
__device__ float d_agg[NNODES * DD];
__device__ float d_gi[NNODES * 3 * DD];
__device__ float d_gh[NNODES * 3 * DD];
__device__ float d_wB1[NLAYERS * 512 * DD];   // [Whh(384) ; Ws^T(128)] per layer
__device__ int   d_off[NNODES + 1];
__device__ int   d_cnt[NNODES];
__device__ int   d_csc[NEDGES];
__device__ float d_pool[NGRAPHS * DD];
__device__ float d_gcnt[NGRAPHS];
__device__ float d_logits[NGRAPHS * NCLASSES];
__device__ int   d_is64;

// ---------------- mma + cp.async helpers ---------------------------------------
__device__ __forceinline__ void mma_tf32(float* c, const uint32_t* a, const uint32_t* b) {
    asm volatile(
        "mma.sync.aligned.m16n8k8.row.col.f32.tf32.tf32.f32 "
        "{%0,%1,%2,%3},{%4,%5,%6,%7},{%8,%9},{%0,%1,%2,%3};"
        : "+f"(c[0]), "+f"(c[1]), "+f"(c[2]), "+f"(c[3])
        : "r"(a[0]), "r"(a[1]), "r"(a[2]), "r"(a[3]), "r"(b[0]), "r"(b[1]));
}
__device__ __forceinline__ void cp_async16(void* smem, const void* gmem, int src_bytes) {
    uint32_t s = (uint32_t)__cvta_generic_to_shared(smem);
    asm volatile("cp.async.cg.shared.global [%0], [%1], 16, %2;"
                 :: "r"(s), "l"(gmem), "r"(src_bytes));
}
__device__ __forceinline__ void cp_commit() {
    asm volatile("cp.async.commit_group;");
}
template <int N>
__device__ __forceinline__ void cp_wait() {
    asm volatile("cp.async.wait_group %0;" :: "n"(N));
}

// ---------------- index dtype detection ---------------------------------------
__global__ void detect_kernel(const void* __restrict__ ei) {
    __shared__ int nz;
    if (threadIdx.x == 0) nz = 0;
    __syncthreads();
    const int* w = (const int*)ei;
    int v = w[2 * threadIdx.x + 1];
    if (v != 0) atomicAdd(&nz, 1);
    __syncthreads();
    if (threadIdx.x == 0) d_is64 = (nz == 0) ? 1 : 0;
}
__device__ __forceinline__ int load_idx(const void* p, int i) {
    return d_is64 ? (int)((const long long*)p)[i] : ((const int*)p)[i];
}

// ---------------- utility kernels ---------------------------------------------
__global__ void copy_h_kernel(const float* __restrict__ src, int n) {
    int i = blockIdx.x * blockDim.x + threadIdx.x;
    if (i < n) d_h[i] = src[i];
}
__global__ void zero_cnt_kernel(int n) {
    int i = blockIdx.x * blockDim.x + threadIdx.x;
    if (i < n) d_cnt[i] = 0;
}
__global__ void zero_pool_kernel() {
    int i = blockIdx.x * blockDim.x + threadIdx.x;
    if (i < NGRAPHS * DD) d_pool[i] = 0.f;
    if (i < NGRAPHS) d_gcnt[i] = 0.f;
}
// B1 = [Whh (rows 0..383) ; Ws^T (rows 384..511)] per layer, fp32
__global__ void conv_wB1_kernel(const float* __restrict__ Whh, const float* __restrict__ Ws) {
    int i = blockIdx.x * blockDim.x + threadIdx.x;
    if (i >= NLAYERS * 512 * DD) return;
    int l = i / (512 * DD);
    int r = (i / DD) % 512;
    int k = i % DD;
    d_wB1[i] = (r < 384) ? Whh[(size_t)l * 384 * DD + r * DD + k]
                         : Ws[(size_t)l * DD * DD + k * DD + (r - 384)];
}

// ---------------- CSC build ----------------------------------------------------
__global__ void count_kernel(const void* __restrict__ ei, int n_edges) {
    int e = blockIdx.x * blockDim.x + threadIdx.x;
    if (e >= n_edges) return;
    int dst = load_idx(ei, n_edges + e);
    if (dst >= 0 && dst < NNODES) atomicAdd(&d_cnt[dst], 1);
}
__global__ void scan_kernel(int n) {
    __shared__ int tmp[1024];
    __shared__ int carry;
    int tid = threadIdx.x;
    if (tid == 0) carry = 0;
    __syncthreads();
    for (int base = 0; base < n; base += 1024) {
        int v = (base + tid < n) ? d_cnt[base + tid] : 0;
        tmp[tid] = v;
        __syncthreads();
        for (int off = 1; off < 1024; off <<= 1) {
            int t = (tid >= off) ? tmp[tid - off] : 0;
            __syncthreads();
            tmp[tid] += t;
            __syncthreads();
        }
        int excl = tmp[tid] - v;
        if (base + tid < n) d_off[base + tid] = carry + excl;
        __syncthreads();
        if (tid == 1023) carry += tmp[1023];
        __syncthreads();
    }
    if (tid == 0) d_off[n] = carry;
}
__global__ void fill_kernel(const void* __restrict__ ei, int n_edges) {
    int e = blockIdx.x * blockDim.x + threadIdx.x;
    if (e >= n_edges) return;
    int dst = load_idx(ei, n_edges + e);
    int src = load_idx(ei, e);
    if (dst < 0 || dst >= NNODES || src < 0 || src >= NNODES) return;
    int pos = d_off[dst] + atomicAdd(&d_cnt[dst], 1);
    if (pos < NEDGES) d_csc[pos] = src;
}

// ---------------- aggregation: one warp per node, float4 per lane --------------
__global__ void agg_kernel(int n_nodes) {
    int warp = (blockIdx.x * blockDim.x + threadIdx.x) >> 5;
    int lane = threadIdx.x & 31;
    if (warp >= n_nodes) return;
    int s = d_off[warp], e = d_off[warp + 1];
    float4 acc = make_float4(0.f, 0.f, 0.f, 0.f);
    for (int i = s; i < e; i++) {
        int src = d_csc[i];
        float4 v = *(const float4*)(d_m + (size_t)src * DD + lane * 4);
        acc.x += v.x; acc.y += v.y; acc.z += v.z; acc.w += v.w;
    }
    *(float4*)(d_agg + (size_t)warp * DD + lane * 4) = acc;
}

// ---------------- 1xTF32 GEMM, BK=32, cp.async double-buffered -----------------
// Raw fp32 fed to mma.tf32 (HW truncates to tf32; no cvt, no reg round trip).
// C[M,:] = A[M,128] @ B[N,128]^T (+bias); cols < N1 -> C1, else C2 (stride 128).
#define SW 36   // row stride 144B (16B-aligned); (4g+tg) mod 32 conflict-free
__device__ __forceinline__ void gemm_tf32_body(
    const float* __restrict__ A, const float* __restrict__ B,
    const float* __restrict__ bias, float* __restrict__ C1, int N1,
    float* __restrict__ C2, int M)
{
    __shared__ float sA[2][128][SW];
    __shared__ float sB[2][64][SW];
    int tid = threadIdx.x, lane = tid & 31, wid = tid >> 5;
    int g = lane >> 2, tg = lane & 3;
    int m0 = blockIdx.x * 128, n0 = blockIdx.y * 64;
    int wm0 = (wid & 3) * 32, wn0 = (wid >> 2) * 32;

    float c[2][4][4] = {};

    // stage chunk kc into buffer p (async; A 4 copies, B 2 copies per thread)
    auto stage = [&](int kc, int p) {
        int k0 = kc * 32;
#pragma unroll
        for (int t = 0; t < 4; t++) {
            int ch = tid + t * 256;
            int row = ch >> 3, q = ch & 7;
            int gr = m0 + row;
            cp_async16(&sA[p][row][q * 4],
                       &A[(size_t)gr * 128 + k0 + q * 4], (gr < M) ? 16 : 0);
        }
#pragma unroll
        for (int t = 0; t < 2; t++) {
            int ch = tid + t * 256;
            int row = ch >> 3, q = ch & 7;
            cp_async16(&sB[p][row][q * 4],
                       &B[(size_t)(n0 + row) * 128 + k0 + q * 4], 16);
        }
        cp_commit();
    };

    stage(0, 0);
    int p = 0;
    for (int kc = 0; kc < 4; kc++) {
        if (kc < 3) {
            stage(kc + 1, p ^ 1);
            cp_wait<1>();   // chunk kc's group complete; kc+1 may be in flight
        } else {
            cp_wait<0>();
        }
        __syncthreads();

#pragma unroll
        for (int ks = 0; ks < 32; ks += 8) {
            // m16n8k8 tf32 fragments:
            //  a0=A[g][tg] a1=A[g+8][tg] a2=A[g][tg+4] a3=A[g+8][tg+4]
            //  b0=B[tg][g] b1=B[tg+4][g]  (B stored [n][k])
            uint32_t ah[2][4], bh[4][2];
#pragma unroll
            for (int mt = 0; mt < 2; mt++) {
                int r0 = wm0 + mt * 16 + g;
                ah[mt][0] = __float_as_uint(sA[p][r0][ks + tg]);
                ah[mt][1] = __float_as_uint(sA[p][r0 + 8][ks + tg]);
                ah[mt][2] = __float_as_uint(sA[p][r0][ks + tg + 4]);
                ah[mt][3] = __float_as_uint(sA[p][r0 + 8][ks + tg + 4]);
            }
#pragma unroll
            for (int nt = 0; nt < 4; nt++) {
                int r = wn0 + nt * 8 + g;
                bh[nt][0] = __float_as_uint(sB[p][r][ks + tg]);
                bh[nt][1] = __float_as_uint(sB[p][r][ks + tg + 4]);
            }
#pragma unroll
            for (int mt = 0; mt < 2; mt++)
#pragma unroll
                for (int nt = 0; nt < 4; nt++)
                    mma_tf32(c[mt][nt], ah[mt], bh[nt]);
        }
        __syncthreads();   // all reads of buf p done before stage(kc+2) overwrites it
        p ^= 1;
    }

#pragma unroll
    for (int mt = 0; mt < 2; mt++)
#pragma unroll
        for (int nt = 0; nt < 4; nt++)
#pragma unroll
            for (int hr = 0; hr < 2; hr++) {
                int row = m0 + wm0 + mt * 16 + g + hr * 8;
                if (row >= M) continue;
                int col = n0 + wn0 + nt * 8 + tg * 2;
                float v0 = c[mt][nt][hr * 2 + 0];
                float v1 = c[mt][nt][hr * 2 + 1];
                if (col < N1) {
                    if (bias) { v0 += bias[col]; v1 += bias[col + 1]; }
                    *(float2*)&C1[(size_t)row * N1 + col] = make_float2(v0, v1);
                } else {
                    *(float2*)&C2[(size_t)row * DD + (col - N1)] = make_float2(v0, v1);
                }
            }
}

// fused: [gh | m] = h @ [Whh^T | Ws]
__global__ __launch_bounds__(256) void gemm1_kernel(const float* __restrict__ bhh, int l, int M) {
    gemm_tf32_body(d_h, d_wB1 + (size_t)l * 512 * DD, bhh, d_gh, 384, d_m, M);
}
// gi = agg @ Wih^T + bih   (Wih already [384,128] row-major = B[n][k])
__global__ __launch_bounds__(256) void gemm2_kernel(const float* __restrict__ Wih,
                                                    const float* __restrict__ bih, int M) {
    gemm_tf32_body(d_agg, Wih, bih, d_gi, 384, nullptr, M);
}

// ---------------- fused GRU gates + ReLU (float4 vectorized) -------------------
__global__ void gru_kernel(int n_nodes) {
    int idx = blockIdx.x * blockDim.x + threadIdx.x;   // one per 4 elements
    int total = n_nodes * (DD / 4);
    if (idx >= total) return;
    int i = idx / (DD / 4), jq = idx % (DD / 4);
    const float* gir = d_gi + (size_t)i * 3 * DD + jq * 4;
    const float* ghr = d_gh + (size_t)i * 3 * DD + jq * 4;
    float4 ir = *(const float4*)(gir);
    float4 iz = *(const float4*)(gir + DD);
    float4 in_ = *(const float4*)(gir + 2 * DD);
    float4 hr = *(const float4*)(ghr);
    float4 hz = *(const float4*)(ghr + DD);
    float4 hn = *(const float4*)(ghr + 2 * DD);
    float4 hv = *(const float4*)(d_h + (size_t)i * DD + jq * 4);
    float4 o;
#define GRU1(f)                                                        \
    {                                                                  \
        float r = 1.f / (1.f + expf(-(ir.f + hr.f)));                  \
        float z = 1.f / (1.f + expf(-(iz.f + hz.f)));                  \
        float nn = tanhf(in_.f + r * hn.f);                            \
        o.f = fmaxf((1.f - z) * nn + z * hv.f, 0.f);                   \
    }
    GRU1(x) GRU1(y) GRU1(z) GRU1(w)
#undef GRU1
    *(float4*)(d_h + (size_t)i * DD + jq * 4) = o;
}

// ---------------- mean pool -----------------------------------------------------
__global__ void pool_kernel(const void* __restrict__ batch, int n_nodes) {
    int idx = blockIdx.x * blockDim.x + threadIdx.x;
    if (idx >= n_nodes * DD) return;
    int i = idx / DD, j = idx % DD;
    int g = load_idx(batch, i);
    if (g < 0 || g >= NGRAPHS) return;
    atomicAdd(&d_pool[g * DD + j], d_h[idx]);
    if (j == 0) atomicAdd(&d_gcnt[g], 1.f);
}

// ---------------- readout FC1(elu) + FC2 ----------------------------------------
__global__ void readout_kernel(const float* __restrict__ fc1w, const float* __restrict__ fc1b,
                               const float* __restrict__ fc2w, const float* __restrict__ fc2b) {
    int g = blockIdx.x;
    int j = threadIdx.x;
    __shared__ float hg[DD];
    __shared__ float h2[DD];
    float c = fmaxf(d_gcnt[g], 1.f);
    hg[j] = d_pool[g * DD + j] / c;
    __syncthreads();
    float a = fc1b[j];
#pragma unroll 4
    for (int k = 0; k < DD; k++) a += hg[k] * fc1w[j * DD + k];
    h2[j] = (a > 0.f) ? a : expm1f(a);
    __syncthreads();
    if (j < NCLASSES) {
        float s = fc2b[j];
#pragma unroll 4
        for (int k = 0; k < DD; k++) s += h2[k] * fc2w[j * DD + k];
        d_logits[g * NCLASSES + j] = s;
    }
}

// ---------------- log_softmax over axis 0 ---------------------------------------
__global__ void lsm_kernel(float* __restrict__ out) {
    int c = blockIdx.x;
    int g = threadIdx.x;
    __shared__ float sh[NGRAPHS];
    float x = d_logits[g * NCLASSES + c];
    sh[g] = x;
    __syncthreads();
    for (int off = NGRAPHS / 2; off > 0; off >>= 1) {
        if (g < off) sh[g] = fmaxf(sh[g], sh[g + off]);
        __syncthreads();
    }
    float mx = sh[0];
    __syncthreads();
    sh[g] = expf(x - mx);
    __syncthreads();
    for (int off = NGRAPHS / 2; off > 0; off >>= 1) {
        if (g < off) sh[g] += sh[g + off];
        __syncthreads();
    }
    float lse = mx + logf(sh[0]);
    out[g * NCLASSES + c] = x - lse;
}

// ---------------- launch ---------------------------------------------------------
extern "C" void kernel_launch(void* const* d_in, const int* in_sizes, int n_in,
                              void* d_out, int out_size) {
    const float* h_in  = (const float*)d_in[0];
    const void*  ei    = d_in[1];
    const void*  batch = d_in[3];
    const float* Ws   = (const float*)d_in[4];
    const float* Wih  = (const float*)d_in[5];
    const float* Whh  = (const float*)d_in[6];
    const float* bih  = (const float*)d_in[7];
    const float* bhh  = (const float*)d_in[8];
    const float* fc1w = (const float*)d_in[9];
    const float* fc1b = (const float*)d_in[10];
    const float* fc2w = (const float*)d_in[11];
    const float* fc2b = (const float*)d_in[12];
    float* out = (float*)d_out;

    int n_nodes = in_sizes[0] / DD;
    int n_edges = in_sizes[1] / 2;
    int nh = n_nodes * DD;

    detect_kernel<<<1, 128>>>(ei);
    copy_h_kernel<<<(nh + 255) / 256, 256>>>(h_in, nh);
    conv_wB1_kernel<<<(NLAYERS * 512 * DD + 255) / 256, 256>>>(Whh, Ws);

    // CSC build (once; reused across layers)
    zero_cnt_kernel<<<(n_nodes + 255) / 256, 256>>>(n_nodes);
    count_kernel<<<(n_edges + 255) / 256, 256>>>(ei, n_edges);
    scan_kernel<<<1, 1024>>>(n_nodes);
    zero_cnt_kernel<<<(n_nodes + 255) / 256, 256>>>(n_nodes);
    fill_kernel<<<(n_edges + 255) / 256, 256>>>(ei, n_edges);

    dim3 grid1((n_nodes + 127) / 128, 8);   // 512 output cols: [gh(384) | m(128)]
    dim3 grid2((n_nodes + 127) / 128, 6);   // 384 output cols: gi

    for (int l = 0; l < NLAYERS; l++) {
        gemm1_kernel<<<grid1, 256>>>(bhh + (size_t)l * 3 * DD, l, n_nodes);
        agg_kernel<<<(n_nodes * 32 + 255) / 256, 256>>>(n_nodes);
        gemm2_kernel<<<grid2, 256>>>(Wih + (size_t)l * 384 * DD, bih + (size_t)l * 3 * DD, n_nodes);
        gru_kernel<<<(nh / 4 + 255) / 256, 256>>>(n_nodes);
    }

    zero_pool_kernel<<<(NGRAPHS * DD + 255) / 256, 256>>>();
    pool_kernel<<<(nh + 255) / 256, 256>>>(batch, n_nodes);
    readout_kernel<<<NGRAPHS, DD>>>(fc1w, fc1b, fc2w, fc2b);
    lsm_kernel<<<NCLASSES, NGRAPHS>>>(out);
}